// round 1
// baseline (speedup 1.0000x reference)
#include <cuda_runtime.h>
#include <math.h>

// Problem constants
#define BB 4
#define CC 192
#define HH 64
#define WW 64
#define HWP 4096           // H*W
#define KIM 1728           // C*9
#define LEAK 0.01f

// ---------------------------------------------------------------------------
// Device scratch (static __device__ arrays — the sanctioned no-alloc route)
// ---------------------------------------------------------------------------
__device__ float g_col [(size_t)BB * KIM * HWP];      // 113 MB  im2col buffer
__device__ float g_tmp [(size_t)BB * CC * HWP];       // 12.6 MB conv1 output
__device__ float g_f1  [(size_t)BB * CC * HWP];       // 12.6 MB theta resblock out
__device__ float g_f2  [(size_t)BB * CC * HWP];       // 12.6 MB phi resblock out
__device__ float g_corr[(size_t)BB * HWP * HWP];      // 256 MB  softmaxed correlation
__device__ float g_corr1[(size_t)BB * 1024 * 1024];   // 16.8 MB pooled corr (level 1)
__device__ float g_corr2[(size_t)BB * 256 * 256];     // 1 MB    pooled corr (level 2)

// ---------------------------------------------------------------------------
// im2col for 3x3 pad-1 conv. x: [B, C, 64, 64] -> col: [B, C*9, 4096]
// col[b][ci*9 + kh*3 + kw][p] = x[b][ci][r+kh-1][c+kw-1] (0 if OOB)
// ---------------------------------------------------------------------------
__global__ void im2col_k(const float* __restrict__ x, float* __restrict__ col) {
    long long idx = (long long)blockIdx.x * blockDim.x + threadIdx.x;
    const long long total = (long long)BB * KIM * HWP;
    if (idx >= total) return;
    int p  = (int)(idx % HWP);
    int ck = (int)((idx / HWP) % KIM);
    int b  = (int)(idx / ((long long)HWP * KIM));
    int ci = ck / 9;
    int k  = ck % 9;
    int r  = p / WW + (k / 3) - 1;
    int c  = p % WW + (k % 3) - 1;
    float v = 0.f;
    if (r >= 0 && r < HH && c >= 0 && c < WW)
        v = x[((long long)b * CC + ci) * HWP + r * WW + c];
    col[idx] = v;
}

// ---------------------------------------------------------------------------
// Generic tiled SGEMM:  C[b][m][n] = sum_k A(b,m,k) * B(b,n,k)
//   A(b,m,k) at A[b*sab + m*sam + k*sak]
//   B(b,n,k) at B[b*sbb + n*sbn + k*sbk]
//   C row-major [M,N], batch stride scb
// epilogue mode: 0 = none
//                1 = leaky(acc + bias[m])
//                2 = leaky(acc + bias[m]) + resid[b*srb + m*N + n]
// Tile 128x128x8, 256 threads, 8x8 micro-tile per thread.
// Requires K % 8 == 0 (true for all our GEMMs: 1728, 192, 4096, 1024, 256).
// ---------------------------------------------------------------------------
__global__ __launch_bounds__(256)
void gemm_k(int M, int N, int K,
            const float* __restrict__ A, long long sam, long long sak, long long sab,
            const float* __restrict__ B, long long sbn, long long sbk, long long sbb,
            float* __restrict__ C, long long scb,
            const float* __restrict__ bias,
            const float* __restrict__ resid, long long srb,
            int mode)
{
    __shared__ float As[8][129];
    __shared__ float Bs[8][129];

    const int tid = threadIdx.x;
    const int tx = tid & 15;         // n direction
    const int ty = tid >> 4;         // m direction
    const int m0 = blockIdx.y * 128;
    const int n0 = blockIdx.x * 128;
    const int b  = blockIdx.z;

    const float* Ab = A + (long long)b * sab;
    const float* Bb = B + (long long)b * sbb;

    const bool amf = (sam == 1);     // m-contiguous A => load m-fast (coalesced)
    const bool bnf = (sbn == 1);     // n-contiguous B => load n-fast (coalesced)

    float acc[8][8];
#pragma unroll
    for (int i = 0; i < 8; i++)
#pragma unroll
        for (int j = 0; j < 8; j++) acc[i][j] = 0.f;

    for (int k0 = 0; k0 < K; k0 += 8) {
        __syncthreads();
        // load A tile (128 x 8) -> As[k][m]
#pragma unroll
        for (int l = 0; l < 4; l++) {
            int idx = tid + l * 256;
            int m, kk;
            if (amf) { m = idx & 127; kk = idx >> 7; }
            else     { kk = idx & 7;  m  = idx >> 3; }
            int gm = m0 + m;
            float v = 0.f;
            if (gm < M)
                v = Ab[(long long)gm * sam + (long long)(k0 + kk) * sak];
            As[kk][m] = v;
        }
        // load B tile (128 x 8) -> Bs[k][n]
#pragma unroll
        for (int l = 0; l < 4; l++) {
            int idx = tid + l * 256;
            int n, kk;
            if (bnf) { n = idx & 127; kk = idx >> 7; }
            else     { kk = idx & 7;  n  = idx >> 3; }
            int gn = n0 + n;
            float v = 0.f;
            if (gn < N)
                v = Bb[(long long)gn * sbn + (long long)(k0 + kk) * sbk];
            Bs[kk][n] = v;
        }
        __syncthreads();

#pragma unroll
        for (int kk = 0; kk < 8; kk++) {
            float a[8], bv[8];
#pragma unroll
            for (int i = 0; i < 8; i++) a[i]  = As[kk][ty + 16 * i];
#pragma unroll
            for (int j = 0; j < 8; j++) bv[j] = Bs[kk][tx + 16 * j];
#pragma unroll
            for (int i = 0; i < 8; i++)
#pragma unroll
                for (int j = 0; j < 8; j++)
                    acc[i][j] += a[i] * bv[j];
        }
    }

    float* Cb = C + (long long)b * scb;
#pragma unroll
    for (int i = 0; i < 8; i++) {
        int gm = m0 + ty + 16 * i;
        if (gm >= M) continue;
        float bvv = (mode >= 1) ? bias[gm] : 0.f;
#pragma unroll
        for (int j = 0; j < 8; j++) {
            int gn = n0 + tx + 16 * j;
            if (gn >= N) continue;
            float v = acc[i][j];
            if (mode >= 1) {
                v += bvv;
                v = (v > 0.f) ? v : LEAK * v;
            }
            if (mode == 2)
                v += resid[(long long)b * srb + (long long)gm * N + gn];
            Cb[(long long)gm * N + gn] = v;
        }
    }
}

// ---------------------------------------------------------------------------
// Row softmax over corr: [B*HW rows] x 4096 cols. One block per row.
// ---------------------------------------------------------------------------
__device__ __forceinline__ float warpMax(float v) {
#pragma unroll
    for (int o = 16; o > 0; o >>= 1) v = fmaxf(v, __shfl_xor_sync(0xffffffffu, v, o));
    return v;
}
__device__ __forceinline__ float warpSum(float v) {
#pragma unroll
    for (int o = 16; o > 0; o >>= 1) v += __shfl_xor_sync(0xffffffffu, v, o);
    return v;
}

__global__ __launch_bounds__(256)
void softmax_k(float* __restrict__ S) {
    long long row = blockIdx.x;
    float* p = S + row * (long long)HWP;
    const int tid = threadIdx.x;
    const int lane = tid & 31;
    const int wid = tid >> 5;

    float v[16];
    float mx = -3.0e38f;
#pragma unroll
    for (int i = 0; i < 16; i++) {
        v[i] = p[tid + 256 * i];
        mx = fmaxf(mx, v[i]);
    }

    __shared__ float smx[8];
    __shared__ float ssum[8];
    mx = warpMax(mx);
    if (lane == 0) smx[wid] = mx;
    __syncthreads();
    if (wid == 0) {
        float t = (lane < 8) ? smx[lane] : -3.0e38f;
        t = warpMax(t);
        if (lane == 0) smx[0] = t;
    }
    __syncthreads();
    mx = smx[0];

    float s = 0.f;
#pragma unroll
    for (int i = 0; i < 16; i++) {
        v[i] = expf(v[i] - mx);
        s += v[i];
    }
    s = warpSum(s);
    if (lane == 0) ssum[wid] = s;
    __syncthreads();
    if (wid == 0) {
        float t = (lane < 8) ? ssum[lane] : 0.f;
        t = warpSum(t);
        if (lane == 0) ssum[0] = t;
    }
    __syncthreads();
    const float inv = 1.f / ssum[0];
#pragma unroll
    for (int i = 0; i < 16; i++)
        p[tid + 256 * i] = v[i] * inv;
}

// ---------------------------------------------------------------------------
// 2x2x2x2 mean pooling of corr on both query and reference grids.
// in: [B, g*g, g*g]  out: [B, (g/2)^2, (g/2)^2]
// ---------------------------------------------------------------------------
__global__ void pool_k(const float* __restrict__ in, float* __restrict__ out, int g) {
    const int g2 = g >> 1;
    const int G2 = g2 * g2;
    const long long G = (long long)g * g;
    const long long total = (long long)BB * G2 * G2;
    long long idx = (long long)blockIdx.x * blockDim.x + threadIdx.x;
    if (idx >= total) return;
    int rp = (int)(idx % G2);
    int qp = (int)((idx / G2) % G2);
    int b  = (int)(idx / ((long long)G2 * G2));
    int Qh = qp / g2, Qw = qp % g2;
    int Rh = rp / g2, Rw = rp % g2;
    const float* base = in + (long long)b * G * G;
    float s = 0.f;
#pragma unroll
    for (int i = 0; i < 2; i++)
#pragma unroll
        for (int j = 0; j < 2; j++) {
            const float* rowp = base + (long long)((2 * Qh + i) * g + 2 * Qw + j) * G
                                     + (long long)(2 * Rh) * g + 2 * Rw;
#pragma unroll
            for (int u = 0; u < 2; u++)
#pragma unroll
                for (int w2 = 0; w2 < 2; w2++)
                    s += rowp[(long long)u * g + w2];
        }
    out[idx] = s * (1.f / 16.f);
}

// ---------------------------------------------------------------------------
// Host orchestration
// ---------------------------------------------------------------------------
static inline void run_gemm(int M, int N, int K,
                            const float* A, long long sam, long long sak, long long sab,
                            const float* B, long long sbn, long long sbk, long long sbb,
                            float* C, long long scb,
                            const float* bias, const float* resid, long long srb,
                            int mode)
{
    dim3 grid((N + 127) / 128, (M + 127) / 128, BB);
    gemm_k<<<grid, 256>>>(M, N, K, A, sam, sak, sab, B, sbn, sbk, sbb,
                          C, scb, bias, resid, srb, mode);
}

extern "C" void kernel_launch(void* const* d_in, const int* in_sizes, int n_in,
                              void* d_out, int out_size)
{
    const float* fd1 = (const float*)d_in[0];
    const float* fd2 = (const float*)d_in[1];
    const float* ref = (const float*)d_in[2];
    const float* o1  = (const float*)d_in[3];
    const float* o2  = (const float*)d_in[4];
    const float* tw1 = (const float*)d_in[5];
    const float* tb1 = (const float*)d_in[6];
    const float* tw2 = (const float*)d_in[7];
    const float* tb2 = (const float*)d_in[8];
    const float* pw1 = (const float*)d_in[9];
    const float* pb1 = (const float*)d_in[10];
    const float* pw2 = (const float*)d_in[11];
    const float* pb2 = (const float*)d_in[12];
    float* out = (float*)d_out;

    float *col, *tmp, *f1, *f2, *corr, *corr1, *corr2;
    cudaGetSymbolAddress((void**)&col,   g_col);
    cudaGetSymbolAddress((void**)&tmp,   g_tmp);
    cudaGetSymbolAddress((void**)&f1,    g_f1);
    cudaGetSymbolAddress((void**)&f2,    g_f2);
    cudaGetSymbolAddress((void**)&corr,  g_corr);
    cudaGetSymbolAddress((void**)&corr1, g_corr1);
    cudaGetSymbolAddress((void**)&corr2, g_corr2);

    const long long featB = (long long)CC * HWP;        // 192*4096
    const long long colB  = (long long)KIM * HWP;       // 1728*4096
    const long long im2colTotal = (long long)BB * KIM * HWP;
    const int im2colGrid = (int)((im2colTotal + 255) / 256);

    // ---- theta resblock: f1 = leaky(conv2(leaky(conv1(fd1)))) + fd1 ----
    im2col_k<<<im2colGrid, 256>>>(fd1, col);
    run_gemm(CC, HWP, KIM,
             tw1, KIM, 1, 0,
             col, 1, HWP, colB,
             tmp, featB, tb1, nullptr, 0, 1);
    im2col_k<<<im2colGrid, 256>>>(tmp, col);
    run_gemm(CC, HWP, KIM,
             tw2, KIM, 1, 0,
             col, 1, HWP, colB,
             f1, featB, tb2, fd1, featB, 2);

    // ---- phi resblock: f2 ----
    im2col_k<<<im2colGrid, 256>>>(fd2, col);
    run_gemm(CC, HWP, KIM,
             pw1, KIM, 1, 0,
             col, 1, HWP, colB,
             tmp, featB, pb1, nullptr, 0, 1);
    im2col_k<<<im2colGrid, 256>>>(tmp, col);
    run_gemm(CC, HWP, KIM,
             pw2, KIM, 1, 0,
             col, 1, HWP, colB,
             f2, featB, pb2, fd2, featB, 2);

    // ---- corr = f1^T f2 : S[q][r] = sum_c f1[c][q] * f2[c][r] ----
    run_gemm(HWP, HWP, CC,
             f1, 1, HWP, featB,
             f2, 1, HWP, featB,
             corr, (long long)HWP * HWP,
             nullptr, nullptr, 0, 0);

    // ---- row softmax ----
    softmax_k<<<BB * HWP, 256>>>(corr);

    // ---- out0[c][q] = sum_r ref[c][r] * corr[q][r] ----
    run_gemm(CC, HWP, HWP,
             ref, HWP, 1, featB,
             corr, HWP, 1, (long long)HWP * HWP,
             out, featB,
             nullptr, nullptr, 0, 0);

    // ---- level 1: pool corr (64-grid) -> corr1, attend to o1 ----
    {
        const long long total = (long long)BB * 1024 * 1024;
        pool_k<<<(int)((total + 255) / 256), 256>>>(corr, corr1, 64);
    }
    run_gemm(CC, 1024, 1024,
             o1, 1024, 1, (long long)CC * 1024,
             corr1, 1024, 1, (long long)1024 * 1024,
             out + (long long)BB * CC * HWP, (long long)CC * 1024,
             nullptr, nullptr, 0, 0);

    // ---- level 2: pool corr1 (32-grid) -> corr2, attend to o2 ----
    {
        const long long total = (long long)BB * 256 * 256;
        pool_k<<<(int)((total + 255) / 256), 256>>>(corr1, corr2, 32);
    }
    run_gemm(CC, 256, 256,
             o2, 256, 1, (long long)CC * 256,
             corr2, 256, 1, (long long)256 * 256,
             out + (long long)BB * CC * HWP + (long long)BB * CC * 1024,
             (long long)CC * 256,
             nullptr, nullptr, 0, 0);

    (void)in_sizes; (void)n_in; (void)out_size;
}

// round 2
// speedup vs baseline: 1.7726x; 1.7726x over previous
#include <cuda_runtime.h>
#include <math.h>

#define BB  4
#define CC  192
#define HWP 4096
#define KIM 1728
#define LEAK 0.01f

// ---------------------------------------------------------------------------
// Device scratch
// ---------------------------------------------------------------------------
__device__ float g_col  [(size_t)BB * KIM * HWP];     // 113 MB
__device__ float g_tmp  [(size_t)BB * CC * HWP];      // 12.6 MB
__device__ float g_f1   [(size_t)BB * CC * HWP];
__device__ float g_f2   [(size_t)BB * CC * HWP];
__device__ float g_corr [(size_t)BB * HWP * HWP];     // 256 MB
__device__ float g_corr1[(size_t)BB * 1024 * 1024];
__device__ float g_corr2[(size_t)BB * 256 * 256];

// ---------------------------------------------------------------------------
// im2col, 4 outputs per thread (float4 store).  x:[B,C,64,64] -> col:[B,C*9,4096]
// ---------------------------------------------------------------------------
__global__ __launch_bounds__(256)
void im2col4_k(const float* __restrict__ x, float* __restrict__ col) {
    int idx = blockIdx.x * 256 + threadIdx.x;          // BB*KIM*1024 = 7,077,888
    const int total = BB * KIM * 1024;
    if (idx >= total) return;
    int p4 = (idx & 1023) << 2;
    int ck = (idx >> 10) % KIM;
    int b  = idx / (1024 * KIM);
    int ci = ck / 9, k = ck % 9;
    int row = (p4 >> 6) + (k / 3) - 1;
    int c0  = (p4 & 63) + (k % 3) - 1;                  // c0 in [-1, 61]
    float4 v = make_float4(0.f, 0.f, 0.f, 0.f);
    if (row >= 0 && row < 64) {
        const float* xr = x + (((long long)b * CC + ci) << 12) + (row << 6);
        v.x = (c0 >= 0)     ? xr[c0]     : 0.f;
        v.y = xr[c0 + 1];
        v.z = xr[c0 + 2];
        v.w = (c0 + 3 < 64) ? xr[c0 + 3] : 0.f;
    }
    reinterpret_cast<float4*>(col)[idx] = v;
}

// ---------------------------------------------------------------------------
// gemmY: TM=64, TN=128, TK=16, 256 threads, 4x8 microtile, double-buffered.
//   C[b][m][n] = sum_k A(b,m,k) * B(b,n,k)
//   A: row-major [M,K] (lda = K), batch stride sab.
//   B: if BN:  [K,N] k-major rows (ldb = N)   (im2col buffer)
//      else:   [N,K] row-major   (ldb = K)    (corr buffers, ref features)
//   MODE: 0 none, 1 leaky(+bias), 2 leaky(+bias)+resid
// Exact sizes assumed: M%64==0, N%128==0, K%16==0.
// ---------------------------------------------------------------------------
template<bool BN, int MODE>
__global__ __launch_bounds__(256)
void gemmY_k(int N, int K,
             const float* __restrict__ A, long long sab,
             const float* __restrict__ B, long long sbb,
             float* __restrict__ C, long long scb,
             const float* __restrict__ bias,
             const float* __restrict__ resid, long long srb)
{
    __shared__ float As[2][16][68];
    __shared__ float Bs[2][16][132];

    const int tid = threadIdx.x;
    const int tx = tid & 15, ty = tid >> 4;
    const int m0 = blockIdx.y << 6;
    const int n0 = blockIdx.x << 7;
    const int b  = blockIdx.z;

    const float* Ab = A + (long long)b * sab;
    const float* Bb = B + (long long)b * sbb;

    // A tile loader indices: 64x16 tile, 1 float4/thread (along k)
    const int am = tid >> 2;
    const int ak = (tid & 3) << 2;
    const float* aptr = Ab + (long long)(m0 + am) * K + ak;

    // B tile loader indices
    const int b_kk = tid >> 5;            // BN path
    const int b_n  = (tid & 31) << 2;
    const int b_nn = tid >> 2;            // !BN path
    const int b_kq = (tid & 3) << 2;
    const float* bptr0;
    const float* bptr1;
    if (BN) {
        bptr0 = Bb + (long long)b_kk * N + n0 + b_n;
        bptr1 = bptr0 + (long long)8 * N;
    } else {
        bptr0 = Bb + (long long)(n0 + b_nn) * K + b_kq;
        bptr1 = bptr0 + (long long)64 * K;
    }

    float4 ra, rb0, rb1;
    float acc[4][8];
#pragma unroll
    for (int i = 0; i < 4; i++)
#pragma unroll
        for (int j = 0; j < 8; j++) acc[i][j] = 0.f;

    // prologue: load tile 0 and store to buffer 0
    ra  = *reinterpret_cast<const float4*>(aptr);
    rb0 = *reinterpret_cast<const float4*>(bptr0);
    rb1 = *reinterpret_cast<const float4*>(bptr1);
    As[0][ak + 0][am] = ra.x;
    As[0][ak + 1][am] = ra.y;
    As[0][ak + 2][am] = ra.z;
    As[0][ak + 3][am] = ra.w;
    if (BN) {
        *reinterpret_cast<float4*>(&Bs[0][b_kk    ][b_n]) = rb0;
        *reinterpret_cast<float4*>(&Bs[0][b_kk + 8][b_n]) = rb1;
    } else {
        Bs[0][b_kq + 0][b_nn] = rb0.x;  Bs[0][b_kq + 0][b_nn + 64] = rb1.x;
        Bs[0][b_kq + 1][b_nn] = rb0.y;  Bs[0][b_kq + 1][b_nn + 64] = rb1.y;
        Bs[0][b_kq + 2][b_nn] = rb0.z;  Bs[0][b_kq + 2][b_nn + 64] = rb1.z;
        Bs[0][b_kq + 3][b_nn] = rb0.w;  Bs[0][b_kq + 3][b_nn + 64] = rb1.w;
    }
    __syncthreads();

    const int NT = K >> 4;
    for (int t = 0; t < NT; t++) {
        const int cur = t & 1;
        const bool more = (t + 1 < NT);
        if (more) {
            ra = *reinterpret_cast<const float4*>(aptr + (t + 1) * 16);
            if (BN) {
                rb0 = *reinterpret_cast<const float4*>(bptr0 + (long long)(t + 1) * 16 * N);
                rb1 = *reinterpret_cast<const float4*>(bptr1 + (long long)(t + 1) * 16 * N);
            } else {
                rb0 = *reinterpret_cast<const float4*>(bptr0 + (t + 1) * 16);
                rb1 = *reinterpret_cast<const float4*>(bptr1 + (t + 1) * 16);
            }
        }
#pragma unroll
        for (int kk = 0; kk < 16; kk++) {
            float4 a  = *reinterpret_cast<const float4*>(&As[cur][kk][ty << 2]);
            float4 b0 = *reinterpret_cast<const float4*>(&Bs[cur][kk][tx << 2]);
            float4 b1 = *reinterpret_cast<const float4*>(&Bs[cur][kk][64 + (tx << 2)]);
            float av[4] = {a.x, a.y, a.z, a.w};
            float bv[8] = {b0.x, b0.y, b0.z, b0.w, b1.x, b1.y, b1.z, b1.w};
#pragma unroll
            for (int i = 0; i < 4; i++)
#pragma unroll
                for (int j = 0; j < 8; j++)
                    acc[i][j] += av[i] * bv[j];
        }
        if (more) {
            const int nxt = cur ^ 1;
            As[nxt][ak + 0][am] = ra.x;
            As[nxt][ak + 1][am] = ra.y;
            As[nxt][ak + 2][am] = ra.z;
            As[nxt][ak + 3][am] = ra.w;
            if (BN) {
                *reinterpret_cast<float4*>(&Bs[nxt][b_kk    ][b_n]) = rb0;
                *reinterpret_cast<float4*>(&Bs[nxt][b_kk + 8][b_n]) = rb1;
            } else {
                Bs[nxt][b_kq + 0][b_nn] = rb0.x;  Bs[nxt][b_kq + 0][b_nn + 64] = rb1.x;
                Bs[nxt][b_kq + 1][b_nn] = rb0.y;  Bs[nxt][b_kq + 1][b_nn + 64] = rb1.y;
                Bs[nxt][b_kq + 2][b_nn] = rb0.z;  Bs[nxt][b_kq + 2][b_nn + 64] = rb1.z;
                Bs[nxt][b_kq + 3][b_nn] = rb0.w;  Bs[nxt][b_kq + 3][b_nn + 64] = rb1.w;
            }
            __syncthreads();
        }
    }

    float* Cb = C + (long long)b * scb + n0 + (tx << 2);
#pragma unroll
    for (int i = 0; i < 4; i++) {
        const int gm = m0 + (ty << 2) + i;
        float4 v0 = make_float4(acc[i][0], acc[i][1], acc[i][2], acc[i][3]);
        float4 v1 = make_float4(acc[i][4], acc[i][5], acc[i][6], acc[i][7]);
        if (MODE >= 1) {
            const float bv = bias[gm];
            v0.x += bv; v0.y += bv; v0.z += bv; v0.w += bv;
            v1.x += bv; v1.y += bv; v1.z += bv; v1.w += bv;
            v0.x = v0.x > 0.f ? v0.x : LEAK * v0.x;
            v0.y = v0.y > 0.f ? v0.y : LEAK * v0.y;
            v0.z = v0.z > 0.f ? v0.z : LEAK * v0.z;
            v0.w = v0.w > 0.f ? v0.w : LEAK * v0.w;
            v1.x = v1.x > 0.f ? v1.x : LEAK * v1.x;
            v1.y = v1.y > 0.f ? v1.y : LEAK * v1.y;
            v1.z = v1.z > 0.f ? v1.z : LEAK * v1.z;
            v1.w = v1.w > 0.f ? v1.w : LEAK * v1.w;
        }
        if (MODE == 2) {
            const float* rp = resid + (long long)b * srb + (long long)gm * N + n0 + (tx << 2);
            const float4 r0 = *reinterpret_cast<const float4*>(rp);
            const float4 r1 = *reinterpret_cast<const float4*>(rp + 64);
            v0.x += r0.x; v0.y += r0.y; v0.z += r0.z; v0.w += r0.w;
            v1.x += r1.x; v1.y += r1.y; v1.z += r1.z; v1.w += r1.w;
        }
        *reinterpret_cast<float4*>(Cb + (long long)gm * N)      = v0;
        *reinterpret_cast<float4*>(Cb + (long long)gm * N + 64) = v1;
    }
}

// ---------------------------------------------------------------------------
// gemmX: corr = f1^T f2.  M=N=4096, K=192.  128x128 tile, 8x8 microtile,
// double-buffered, all-float4. A(m,k)=f1[k*4096+m], B(n,k)=f2[k*4096+n].
// ---------------------------------------------------------------------------
__global__ __launch_bounds__(256)
void gemmX_k(const float* __restrict__ A, const float* __restrict__ B,
             float* __restrict__ C)
{
    __shared__ float As[2][16][128];
    __shared__ float Bs[2][16][128];

    const int tid = threadIdx.x;
    const int tx = tid & 15, ty = tid >> 4;
    const int m0 = blockIdx.y << 7;
    const int n0 = blockIdx.x << 7;
    const int b  = blockIdx.z;

    const float* Ab = A + (long long)b * (CC * HWP);
    const float* Bb = B + (long long)b * (CC * HWP);

    const int lk = tid >> 5;               // 0..7
    const int ln = (tid & 31) << 2;        // 0..124
    const float* ap0 = Ab + (long long)lk * HWP + m0 + ln;
    const float* bp0 = Bb + (long long)lk * HWP + n0 + ln;

    float4 ra0, ra1, rb0, rb1;
    float acc[8][8];
#pragma unroll
    for (int i = 0; i < 8; i++)
#pragma unroll
        for (int j = 0; j < 8; j++) acc[i][j] = 0.f;

    ra0 = *reinterpret_cast<const float4*>(ap0);
    ra1 = *reinterpret_cast<const float4*>(ap0 + 8 * HWP);
    rb0 = *reinterpret_cast<const float4*>(bp0);
    rb1 = *reinterpret_cast<const float4*>(bp0 + 8 * HWP);
    *reinterpret_cast<float4*>(&As[0][lk    ][ln]) = ra0;
    *reinterpret_cast<float4*>(&As[0][lk + 8][ln]) = ra1;
    *reinterpret_cast<float4*>(&Bs[0][lk    ][ln]) = rb0;
    *reinterpret_cast<float4*>(&Bs[0][lk + 8][ln]) = rb1;
    __syncthreads();

    const int NT = CC >> 4;                // 12
    for (int t = 0; t < NT; t++) {
        const int cur = t & 1;
        const bool more = (t + 1 < NT);
        if (more) {
            const float* ap = ap0 + (long long)(t + 1) * 16 * HWP;
            const float* bp = bp0 + (long long)(t + 1) * 16 * HWP;
            ra0 = *reinterpret_cast<const float4*>(ap);
            ra1 = *reinterpret_cast<const float4*>(ap + 8 * HWP);
            rb0 = *reinterpret_cast<const float4*>(bp);
            rb1 = *reinterpret_cast<const float4*>(bp + 8 * HWP);
        }
#pragma unroll
        for (int kk = 0; kk < 16; kk++) {
            float4 a0 = *reinterpret_cast<const float4*>(&As[cur][kk][ty << 2]);
            float4 a1 = *reinterpret_cast<const float4*>(&As[cur][kk][64 + (ty << 2)]);
            float4 b0 = *reinterpret_cast<const float4*>(&Bs[cur][kk][tx << 2]);
            float4 b1 = *reinterpret_cast<const float4*>(&Bs[cur][kk][64 + (tx << 2)]);
            float av[8] = {a0.x, a0.y, a0.z, a0.w, a1.x, a1.y, a1.z, a1.w};
            float bv[8] = {b0.x, b0.y, b0.z, b0.w, b1.x, b1.y, b1.z, b1.w};
#pragma unroll
            for (int i = 0; i < 8; i++)
#pragma unroll
                for (int j = 0; j < 8; j++)
                    acc[i][j] += av[i] * bv[j];
        }
        if (more) {
            const int nxt = cur ^ 1;
            *reinterpret_cast<float4*>(&As[nxt][lk    ][ln]) = ra0;
            *reinterpret_cast<float4*>(&As[nxt][lk + 8][ln]) = ra1;
            *reinterpret_cast<float4*>(&Bs[nxt][lk    ][ln]) = rb0;
            *reinterpret_cast<float4*>(&Bs[nxt][lk + 8][ln]) = rb1;
            __syncthreads();
        }
    }

    float* Cb = C + (long long)b * ((long long)HWP * HWP) + n0 + (tx << 2);
#pragma unroll
    for (int ih = 0; ih < 2; ih++) {
#pragma unroll
        for (int i = 0; i < 4; i++) {
            const int gm = m0 + ih * 64 + (ty << 2) + i;
            const int ai = ih * 4 + i;
            float4 v0 = make_float4(acc[ai][0], acc[ai][1], acc[ai][2], acc[ai][3]);
            float4 v1 = make_float4(acc[ai][4], acc[ai][5], acc[ai][6], acc[ai][7]);
            *reinterpret_cast<float4*>(Cb + (long long)gm * HWP)      = v0;
            *reinterpret_cast<float4*>(Cb + (long long)gm * HWP + 64) = v1;
        }
    }
}

// ---------------------------------------------------------------------------
// Row softmax, float4, __expf. 4096 cols, one block (256 thr) per row.
// ---------------------------------------------------------------------------
__device__ __forceinline__ float warpMax(float v) {
#pragma unroll
    for (int o = 16; o > 0; o >>= 1) v = fmaxf(v, __shfl_xor_sync(0xffffffffu, v, o));
    return v;
}
__device__ __forceinline__ float warpSum(float v) {
#pragma unroll
    for (int o = 16; o > 0; o >>= 1) v += __shfl_xor_sync(0xffffffffu, v, o);
    return v;
}

__global__ __launch_bounds__(256)
void softmax4_k(float* __restrict__ S) {
    float4* p = reinterpret_cast<float4*>(S + (long long)blockIdx.x * HWP);
    const int tid = threadIdx.x;
    const int lane = tid & 31, wid = tid >> 5;

    float4 v[4];
    float mx = -3.0e38f;
#pragma unroll
    for (int i = 0; i < 4; i++) {
        v[i] = p[tid + 256 * i];
        mx = fmaxf(mx, fmaxf(fmaxf(v[i].x, v[i].y), fmaxf(v[i].z, v[i].w)));
    }
    __shared__ float red[8];
    mx = warpMax(mx);
    if (lane == 0) red[wid] = mx;
    __syncthreads();
    if (wid == 0) {
        float t = (lane < 8) ? red[lane] : -3.0e38f;
        t = warpMax(t);
        if (lane == 0) red[0] = t;
    }
    __syncthreads();
    mx = red[0];
    __syncthreads();

    float s = 0.f;
#pragma unroll
    for (int i = 0; i < 4; i++) {
        v[i].x = __expf(v[i].x - mx);
        v[i].y = __expf(v[i].y - mx);
        v[i].z = __expf(v[i].z - mx);
        v[i].w = __expf(v[i].w - mx);
        s += v[i].x + v[i].y + v[i].z + v[i].w;
    }
    s = warpSum(s);
    if (lane == 0) red[wid] = s;
    __syncthreads();
    if (wid == 0) {
        float t = (lane < 8) ? red[lane] : 0.f;
        t = warpSum(t);
        if (lane == 0) red[0] = t;
    }
    __syncthreads();
    const float inv = 1.f / red[0];
#pragma unroll
    for (int i = 0; i < 4; i++) {
        v[i].x *= inv; v[i].y *= inv; v[i].z *= inv; v[i].w *= inv;
        p[tid + 256 * i] = v[i];
    }
}

// ---------------------------------------------------------------------------
// 2x2x2x2 mean pool on both grids: in [B, g^2, g^2] -> out [B, (g/2)^2, (g/2)^2]
// Each thread computes 2 adjacent outputs (float2 loads/stores).
// ---------------------------------------------------------------------------
__global__ __launch_bounds__(256)
void pool2_k(const float* __restrict__ in, float* __restrict__ out, int g) {
    const int g2 = g >> 1;
    const int G2 = g2 * g2;
    const int halfP = G2 >> 1;
    const long long total = (long long)BB * G2 * halfP;
    long long idx = (long long)blockIdx.x * 256 + threadIdx.x;
    if (idx >= total) return;
    int t  = (int)(idx % halfP);
    int qp = (int)((idx / halfP) % G2);
    int b  = (int)(idx / ((long long)halfP * G2));
    const int Rh  = (2 * t) / g2;
    const int Rw0 = (2 * t) % g2;
    const int Qh = qp / g2, Qw = qp % g2;
    const long long G = (long long)g * g;
    const float* base = in + (long long)b * G * G;
    float s0 = 0.f, s1 = 0.f;
#pragma unroll
    for (int i = 0; i < 2; i++)
#pragma unroll
        for (int j = 0; j < 2; j++) {
            const float* qrow = base + ((long long)((2 * Qh + i) * g + 2 * Qw + j)) * G;
#pragma unroll
            for (int u = 0; u < 2; u++) {
                const float2* rp = reinterpret_cast<const float2*>(
                    qrow + (long long)(2 * Rh + u) * g + 2 * Rw0);
                float2 x0 = rp[0], x1 = rp[1];
                s0 += x0.x + x0.y;
                s1 += x1.x + x1.y;
            }
        }
    float2 o = make_float2(s0 * (1.f / 16.f), s1 * (1.f / 16.f));
    *reinterpret_cast<float2*>(out + ((long long)b * G2 + qp) * G2 + 2 * t) = o;
}

// ---------------------------------------------------------------------------
// Host orchestration
// ---------------------------------------------------------------------------
extern "C" void kernel_launch(void* const* d_in, const int* in_sizes, int n_in,
                              void* d_out, int out_size)
{
    const float* fd1 = (const float*)d_in[0];
    const float* fd2 = (const float*)d_in[1];
    const float* ref = (const float*)d_in[2];
    const float* o1  = (const float*)d_in[3];
    const float* o2  = (const float*)d_in[4];
    const float* tw1 = (const float*)d_in[5];
    const float* tb1 = (const float*)d_in[6];
    const float* tw2 = (const float*)d_in[7];
    const float* tb2 = (const float*)d_in[8];
    const float* pw1 = (const float*)d_in[9];
    const float* pb1 = (const float*)d_in[10];
    const float* pw2 = (const float*)d_in[11];
    const float* pb2 = (const float*)d_in[12];
    float* out = (float*)d_out;

    float *col, *tmp, *f1, *f2, *corr, *corr1, *corr2;
    cudaGetSymbolAddress((void**)&col,   g_col);
    cudaGetSymbolAddress((void**)&tmp,   g_tmp);
    cudaGetSymbolAddress((void**)&f1,    g_f1);
    cudaGetSymbolAddress((void**)&f2,    g_f2);
    cudaGetSymbolAddress((void**)&corr,  g_corr);
    cudaGetSymbolAddress((void**)&corr1, g_corr1);
    cudaGetSymbolAddress((void**)&corr2, g_corr2);

    const long long featB = (long long)CC * HWP;
    const long long colB  = (long long)KIM * HWP;
    const int im2colGrid  = (BB * KIM * 1024 + 255) / 256;

    const dim3 convGrid(HWP / 128, CC / 64, BB);       // (32, 3, 4)

    // ---- theta resblock ----
    im2col4_k<<<im2colGrid, 256>>>(fd1, col);
    gemmY_k<true, 1><<<convGrid, 256>>>(HWP, KIM, tw1, 0, col, colB,
                                        tmp, featB, tb1, nullptr, 0);
    im2col4_k<<<im2colGrid, 256>>>(tmp, col);
    gemmY_k<true, 2><<<convGrid, 256>>>(HWP, KIM, tw2, 0, col, colB,
                                        f1, featB, tb2, fd1, featB);

    // ---- phi resblock ----
    im2col4_k<<<im2colGrid, 256>>>(fd2, col);
    gemmY_k<true, 1><<<convGrid, 256>>>(HWP, KIM, pw1, 0, col, colB,
                                        tmp, featB, pb1, nullptr, 0);
    im2col4_k<<<im2colGrid, 256>>>(tmp, col);
    gemmY_k<true, 2><<<convGrid, 256>>>(HWP, KIM, pw2, 0, col, colB,
                                        f2, featB, pb2, fd2, featB);

    // ---- corr = f1^T f2 ----
    {
        dim3 grid(HWP / 128, HWP / 128, BB);            // (32, 32, 4)
        gemmX_k<<<grid, 256>>>(f1, f2, corr);
    }

    // ---- row softmax ----
    softmax4_k<<<BB * HWP, 256>>>(corr);

    // ---- out0: M=192, N=4096, K=4096 ----
    gemmY_k<false, 0><<<convGrid, 256>>>(HWP, HWP, ref, featB,
                                         corr, (long long)HWP * HWP,
                                         out, featB, nullptr, nullptr, 0);

    // ---- level 1 ----
    {
        const long long total = (long long)BB * 1024 * 512;
        pool2_k<<<(int)((total + 255) / 256), 256>>>(corr, corr1, 64);
        dim3 grid(1024 / 128, CC / 64, BB);             // (8, 3, 4)
        gemmY_k<false, 0><<<grid, 256>>>(1024, 1024, o1, (long long)CC * 1024,
                                         corr1, (long long)1024 * 1024,
                                         out + (long long)BB * CC * HWP,
                                         (long long)CC * 1024, nullptr, nullptr, 0);
    }

    // ---- level 2 ----
    {
        const long long total = (long long)BB * 256 * 128;
        pool2_k<<<(int)((total + 255) / 256), 256>>>(corr1, corr2, 32);
        dim3 grid(256 / 128, CC / 64, BB);              // (2, 3, 4)
        gemmY_k<false, 0><<<grid, 256>>>(256, 256, o2, (long long)CC * 256,
                                         corr2, (long long)256 * 256,
                                         out + (long long)BB * CC * HWP + (long long)BB * CC * 1024,
                                         (long long)CC * 256, nullptr, nullptr, 0);
    }

    (void)in_sizes; (void)n_in; (void)out_size;
}